// round 8
// baseline (speedup 1.0000x reference)
#include <cuda_runtime.h>

// ---------------------------------------------------------------------------
// Problem constants
// ---------------------------------------------------------------------------
#define D_MODEL 2048
#define NHEADS  16
#define DHEAD   128
#define SEQ     2048
#define BATCH   2
#define MTOT    (BATCH * SEQ)        // 4096 rows
#define OUTSZ   (MTOT * D_MODEL)     // 8388608 elements per output tensor

// Scratch buffers (no cudaMalloc allowed -> device globals)
__device__ float g_q [MTOT * D_MODEL];  // q  (then qn in-place)
__device__ float g_kn[MTOT * D_MODEL];  // normalized k
__device__ float g_z [MTOT * D_MODEL];  // attention output (pre out-proj)

// ---------------------------------------------------------------------------
// GEMM: C[m,n] = sum_k A[m,k] * B[n,k] + bias[n]     (A:[M,K], B:[N,K] row-major)
// Output routed into up-to-3 segment pointers of width segN each.
// BM=BN=128, BK=16, 256 threads, 8x8 per thread (4+64 split), double buffered.
// ---------------------------------------------------------------------------
#define BM 128
#define BN 128
#define BK 16

__global__ __launch_bounds__(256, 2)
void gemm_bias_nt(const float* __restrict__ A, const float* __restrict__ B,
                  const float* __restrict__ bias,
                  float* __restrict__ out0, float* __restrict__ out1,
                  float* __restrict__ out2,
                  int M, int N, int K, int segN)
{
    __shared__ __align__(16) float As[2][BK][BM];
    __shared__ __align__(16) float Bs[2][BK][BN];

    const int tid = threadIdx.x;
    const int tx  = tid & 15;
    const int ty  = tid >> 4;
    const int m0  = blockIdx.y * BM;
    const int n0  = blockIdx.x * BN;

    const float* Ab = A + (size_t)m0 * K;
    const float* Bb = B + (size_t)n0 * K;

    float acc[8][8];
#pragma unroll
    for (int i = 0; i < 8; i++)
#pragma unroll
        for (int j = 0; j < 8; j++) acc[i][j] = 0.f;

    // load tile 0
#pragma unroll
    for (int i = 0; i < 2; i++) {
        int idx = tid + i * 256;
        int row = idx >> 2;
        int kg  = (idx & 3) << 2;
        float4 av = *(const float4*)(Ab + (size_t)row * K + kg);
        As[0][kg + 0][row] = av.x; As[0][kg + 1][row] = av.y;
        As[0][kg + 2][row] = av.z; As[0][kg + 3][row] = av.w;
        float4 bv = *(const float4*)(Bb + (size_t)row * K + kg);
        Bs[0][kg + 0][row] = bv.x; Bs[0][kg + 1][row] = bv.y;
        Bs[0][kg + 2][row] = bv.z; Bs[0][kg + 3][row] = bv.w;
    }
    __syncthreads();

    const int ntiles = K / BK;
    for (int t = 0; t < ntiles; t++) {
        const int cur = t & 1;
        float4 ra[2], rb[2];
        if (t + 1 < ntiles) {
            const int k0 = (t + 1) * BK;
#pragma unroll
            for (int i = 0; i < 2; i++) {
                int idx = tid + i * 256;
                int row = idx >> 2;
                int kg  = (idx & 3) << 2;
                ra[i] = *(const float4*)(Ab + (size_t)row * K + k0 + kg);
                rb[i] = *(const float4*)(Bb + (size_t)row * K + k0 + kg);
            }
        }
#pragma unroll
        for (int kk = 0; kk < BK; kk++) {
            float a[8], b[8];
            *(float4*)&a[0] = *(const float4*)&As[cur][kk][ty * 4];
            *(float4*)&a[4] = *(const float4*)&As[cur][kk][ty * 4 + 64];
            *(float4*)&b[0] = *(const float4*)&Bs[cur][kk][tx * 4];
            *(float4*)&b[4] = *(const float4*)&Bs[cur][kk][tx * 4 + 64];
#pragma unroll
            for (int i = 0; i < 8; i++)
#pragma unroll
                for (int j = 0; j < 8; j++)
                    acc[i][j] += a[i] * b[j];
        }
        if (t + 1 < ntiles) {
            const int nxt = cur ^ 1;
#pragma unroll
            for (int i = 0; i < 2; i++) {
                int idx = tid + i * 256;
                int row = idx >> 2;
                int kg  = (idx & 3) << 2;
                As[nxt][kg + 0][row] = ra[i].x; As[nxt][kg + 1][row] = ra[i].y;
                As[nxt][kg + 2][row] = ra[i].z; As[nxt][kg + 3][row] = ra[i].w;
                Bs[nxt][kg + 0][row] = rb[i].x; Bs[nxt][kg + 1][row] = rb[i].y;
                Bs[nxt][kg + 2][row] = rb[i].z; Bs[nxt][kg + 3][row] = rb[i].w;
            }
            __syncthreads();
        }
    }

    // epilogue: bias + segmented store (each 128-wide block tile lies in one segment)
#pragma unroll
    for (int i = 0; i < 8; i++) {
        const int gm = m0 + ((i < 4) ? (ty * 4 + i) : (64 + ty * 4 + (i - 4)));
#pragma unroll
        for (int jh = 0; jh < 2; jh++) {
            const int gn  = n0 + tx * 4 + jh * 64;
            const int seg = gn / segN;
            float* o = (seg == 0) ? out0 : ((seg == 1) ? out1 : out2);
            float4 v;
            v.x = acc[i][jh * 4 + 0] + bias[gn + 0];
            v.y = acc[i][jh * 4 + 1] + bias[gn + 1];
            v.z = acc[i][jh * 4 + 2] + bias[gn + 2];
            v.w = acc[i][jh * 4 + 3] + bias[gn + 3];
            *(float4*)(o + (size_t)gm * segN + (gn - seg * segN)) = v;
        }
    }
}

// ---------------------------------------------------------------------------
// RMSNorm over contiguous 128-float vectors: out = x * rsqrt(mean(x^2)+eps) * w
// one warp per vector; grid.x * 8 vectors total
// ---------------------------------------------------------------------------
__global__ __launch_bounds__(256)
void rmsnorm128(const float* __restrict__ in, float* __restrict__ out,
                const float* __restrict__ w)
{
    const int row  = blockIdx.x * 8 + (threadIdx.x >> 5);
    const int lane = threadIdx.x & 31;
    const size_t base = (size_t)row * DHEAD + lane * 4;
    float4 xv = *(const float4*)(in + base);
    float ss = xv.x * xv.x + xv.y * xv.y + xv.z * xv.z + xv.w * xv.w;
#pragma unroll
    for (int msk = 16; msk; msk >>= 1)
        ss += __shfl_xor_sync(0xffffffffu, ss, msk);
    const float r = rsqrtf(ss * (1.0f / 128.0f) + 1e-6f);
    float4 wv = *(const float4*)(w + lane * 4);
    float4 ov;
    ov.x = xv.x * r * wv.x;
    ov.y = xv.y * r * wv.y;
    ov.z = xv.z * r * wv.z;
    ov.w = xv.w * r * wv.w;
    *(float4*)(out + base) = ov;
}

// ---------------------------------------------------------------------------
// Flash attention (non-causal, scale = 1.0), fp32.
// Grid: (SEQ/BQ, NHEADS, BATCH). Block: 256 threads (16x16).
// Q/K/V logical [b, s, h, dh] with row stride D_MODEL, head offset h*DHEAD.
// BQ=BKT=64. Per thread: 4x4 of S, 4 rows x 8 cols of O.
// ---------------------------------------------------------------------------
#define BQ    64
#define BKT   64
#define QPAD  132   // Qs row stride (floats)   - breaks 128-stride bank clash
#define KTPAD 68    // KsT row stride (floats)
#define PPAD  65    // Ps row stride (floats)

#define ATTN_SMEM_FLOATS (BQ * QPAD + DHEAD * KTPAD + BKT * DHEAD + BQ * PPAD)

__global__ __launch_bounds__(256, 1)
void attn_flash(const float* __restrict__ Q, const float* __restrict__ Kn,
                const float* __restrict__ V, float* __restrict__ Z)
{
    extern __shared__ __align__(16) float sm[];
    float* Qs  = sm;                        // [BQ][QPAD]
    float* KsT = Qs  + BQ * QPAD;           // [DHEAD][KTPAD]  (transposed K)
    float* Vs  = KsT + DHEAD * KTPAD;       // [BKT][DHEAD]
    float* Ps  = Vs  + BKT * DHEAD;         // [BQ][PPAD]

    const int tid = threadIdx.x;
    const int tx  = tid & 15;
    const int ty  = tid >> 4;
    const int qt  = blockIdx.x;
    const int h   = blockIdx.y;
    const int b   = blockIdx.z;

    const size_t rowbase = (size_t)b * SEQ;
    const int    hb      = h * DHEAD;
    const int    q0      = qt * BQ;

    // Load Q tile (reused for all K tiles)
    for (int idx = tid; idx < BQ * (DHEAD / 4); idx += 256) {
        int i  = idx >> 5;
        int d4 = (idx & 31) << 2;
        float4 v = *(const float4*)(Q + (rowbase + q0 + i) * D_MODEL + hb + d4);
        *(float4*)(Qs + i * QPAD + d4) = v;
    }

    float o[4][8];
    float mrow[4], lrow[4];
#pragma unroll
    for (int r = 0; r < 4; r++) {
        mrow[r] = -1e30f;
        lrow[r] = 0.f;
#pragma unroll
        for (int c = 0; c < 8; c++) o[r][c] = 0.f;
    }

    for (int kt = 0; kt < SEQ / BKT; kt++) {
        __syncthreads();   // prior PV done reading Vs/Ps; also orders Qs on iter 0
        const int k0 = kt * BKT;
        for (int idx = tid; idx < BKT * (DHEAD / 4); idx += 256) {
            int j  = idx >> 5;
            int d4 = (idx & 31) << 2;
            float4 kv = *(const float4*)(Kn + (rowbase + k0 + j) * D_MODEL + hb + d4);
            KsT[(d4 + 0) * KTPAD + j] = kv.x;
            KsT[(d4 + 1) * KTPAD + j] = kv.y;
            KsT[(d4 + 2) * KTPAD + j] = kv.z;
            KsT[(d4 + 3) * KTPAD + j] = kv.w;
            float4 vv = *(const float4*)(V + (rowbase + k0 + j) * D_MODEL + hb + d4);
            *(float4*)(Vs + j * DHEAD + d4) = vv;
        }
        __syncthreads();

        // S = Q K^T   (4x4 per thread)
        float s[4][4];
#pragma unroll
        for (int r = 0; r < 4; r++)
#pragma unroll
            for (int c = 0; c < 4; c++) s[r][c] = 0.f;

#pragma unroll 8
        for (int d = 0; d < DHEAD; d++) {
            float4 kf = *(const float4*)(KsT + d * KTPAD + tx * 4);
            float qa = Qs[(ty * 4 + 0) * QPAD + d];
            float qb = Qs[(ty * 4 + 1) * QPAD + d];
            float qc = Qs[(ty * 4 + 2) * QPAD + d];
            float qd = Qs[(ty * 4 + 3) * QPAD + d];
            s[0][0] += qa * kf.x; s[0][1] += qa * kf.y; s[0][2] += qa * kf.z; s[0][3] += qa * kf.w;
            s[1][0] += qb * kf.x; s[1][1] += qb * kf.y; s[1][2] += qb * kf.z; s[1][3] += qb * kf.w;
            s[2][0] += qc * kf.x; s[2][1] += qc * kf.y; s[2][2] += qc * kf.z; s[2][3] += qc * kf.w;
            s[3][0] += qd * kf.x; s[3][1] += qd * kf.y; s[3][2] += qd * kf.z; s[3][3] += qd * kf.w;
        }

        // online softmax update (row reductions across the 16 tx lanes)
#pragma unroll
        for (int r = 0; r < 4; r++) {
            float mx = fmaxf(fmaxf(s[r][0], s[r][1]), fmaxf(s[r][2], s[r][3]));
#pragma unroll
            for (int msk = 8; msk; msk >>= 1)
                mx = fmaxf(mx, __shfl_xor_sync(0xffffffffu, mx, msk));
            const float mnew = fmaxf(mrow[r], mx);
            const float corr = __expf(mrow[r] - mnew);
            float rs = 0.f;
#pragma unroll
            for (int c = 0; c < 4; c++) {
                float p = __expf(s[r][c] - mnew);
                Ps[(ty * 4 + r) * PPAD + tx * 4 + c] = p;
                rs += p;
            }
#pragma unroll
            for (int msk = 8; msk; msk >>= 1)
                rs += __shfl_xor_sync(0xffffffffu, rs, msk);
            lrow[r] = lrow[r] * corr + rs;
            mrow[r] = mnew;
#pragma unroll
            for (int c = 0; c < 8; c++) o[r][c] *= corr;
        }
        __syncthreads();

        // O += P V
#pragma unroll 4
        for (int k = 0; k < BKT; k++) {
            float4 v0 = *(const float4*)(Vs + k * DHEAD + tx * 8);
            float4 v1 = *(const float4*)(Vs + k * DHEAD + tx * 8 + 4);
#pragma unroll
            for (int r = 0; r < 4; r++) {
                float p = Ps[(ty * 4 + r) * PPAD + k];
                o[r][0] += p * v0.x; o[r][1] += p * v0.y;
                o[r][2] += p * v0.z; o[r][3] += p * v0.w;
                o[r][4] += p * v1.x; o[r][5] += p * v1.y;
                o[r][6] += p * v1.z; o[r][7] += p * v1.w;
            }
        }
    }

    // normalize and write Z in [b, s, h*dh] layout
#pragma unroll
    for (int r = 0; r < 4; r++) {
        const float inv = 1.f / lrow[r];
        float4 w0, w1;
        w0.x = o[r][0] * inv; w0.y = o[r][1] * inv;
        w0.z = o[r][2] * inv; w0.w = o[r][3] * inv;
        w1.x = o[r][4] * inv; w1.y = o[r][5] * inv;
        w1.z = o[r][6] * inv; w1.w = o[r][7] * inv;
        const size_t base = (rowbase + q0 + ty * 4 + r) * D_MODEL + hb + tx * 8;
        *(float4*)(Z + base)     = w0;
        *(float4*)(Z + base + 4) = w1;
    }
}

// ---------------------------------------------------------------------------
// Launch
// Inputs (metadata order): x, W_qkv, b_qkv, W_o, b_o, wq, wk   (all fp32)
// Output: [out | k_new | v_new], each MTOT*D_MODEL floats.
// ---------------------------------------------------------------------------
extern "C" void kernel_launch(void* const* d_in, const int* in_sizes, int n_in,
                              void* d_out, int out_size)
{
    const float* x    = (const float*)d_in[0];
    const float* Wqkv = (const float*)d_in[1];
    const float* bqkv = (const float*)d_in[2];
    const float* Wo   = (const float*)d_in[3];
    const float* bo   = (const float*)d_in[4];
    const float* wq   = (const float*)d_in[5];
    const float* wk   = (const float*)d_in[6];

    float* out  = (float*)d_out;
    float* kout = out + (size_t)OUTSZ;       // k_new (pre-norm)
    float* vout = out + (size_t)2 * OUTSZ;   // v_new

    float *qbuf = nullptr, *knbuf = nullptr, *zbuf = nullptr;
    cudaGetSymbolAddress((void**)&qbuf,  g_q);
    cudaGetSymbolAddress((void**)&knbuf, g_kn);
    cudaGetSymbolAddress((void**)&zbuf,  g_z);

    // 1) QKV projection: q -> scratch, k/v -> their output regions directly
    gemm_bias_nt<<<dim3(3 * D_MODEL / BN, MTOT / BM), 256>>>(
        x, Wqkv, bqkv, qbuf, kout, vout,
        MTOT, 3 * D_MODEL, D_MODEL, D_MODEL);

    // 2) per-head RMSNorm on q (in place) and k (into scratch)
    rmsnorm128<<<(MTOT * NHEADS) / 8, 256>>>(qbuf, qbuf, wq);
    rmsnorm128<<<(MTOT * NHEADS) / 8, 256>>>(kout, knbuf, wk);

    // 3) flash attention -> z scratch
    const int attn_smem = ATTN_SMEM_FLOATS * (int)sizeof(float);
    cudaFuncSetAttribute(attn_flash,
                         cudaFuncAttributeMaxDynamicSharedMemorySize, attn_smem);
    attn_flash<<<dim3(SEQ / BQ, NHEADS, BATCH), 256, attn_smem>>>(
        qbuf, knbuf, vout, zbuf);

    // 4) output projection
    gemm_bias_nt<<<dim3(D_MODEL / BN, MTOT / BM), 256>>>(
        zbuf, Wo, bo, out, out, out,
        MTOT, D_MODEL, D_MODEL, D_MODEL);
}

// round 9
// speedup vs baseline: 1.0429x; 1.0429x over previous
#include <cuda_runtime.h>

// ---------------------------------------------------------------------------
// Problem constants
// ---------------------------------------------------------------------------
#define D_MODEL 2048
#define NHEADS  16
#define DHEAD   128
#define SEQ     2048
#define BATCH   2
#define MTOT    (BATCH * SEQ)        // 4096 rows
#define OUTSZ   (MTOT * D_MODEL)     // 8388608 elements per output tensor

// Scratch buffers (no cudaMalloc allowed -> device globals)
__device__ float g_q [MTOT * D_MODEL];  // q  (then qn in-place)
__device__ float g_kn[MTOT * D_MODEL];  // normalized k
__device__ float g_z [MTOT * D_MODEL];  // attention output (pre out-proj)

// ---------------------------------------------------------------------------
// Packed fp32x2 helpers (Blackwell FFMA2 path: full-rate fp32)
// ---------------------------------------------------------------------------
typedef unsigned long long u64;

__device__ __forceinline__ u64 f2_pack(float lo, float hi) {
    u64 r; asm("mov.b64 %0, {%1, %2};" : "=l"(r) : "f"(lo), "f"(hi)); return r;
}
__device__ __forceinline__ u64 f2_dup(float x) { return f2_pack(x, x); }
__device__ __forceinline__ void f2_fma(u64& d, u64 a, u64 b) {
    asm("fma.rn.f32x2 %0, %1, %2, %0;" : "+l"(d) : "l"(a), "l"(b));
}
__device__ __forceinline__ u64 f2_mul(u64 a, u64 b) {
    u64 r; asm("mul.rn.f32x2 %0, %1, %2;" : "=l"(r) : "l"(a), "l"(b)); return r;
}
__device__ __forceinline__ void f2_unpack(u64 v, float& lo, float& hi) {
    asm("mov.b64 {%0, %1}, %2;" : "=f"(lo), "=f"(hi) : "l"(v));
}

// ---------------------------------------------------------------------------
// GEMM: C[m,n] = sum_k A[m,k] * B[n,k] + bias[n]     (A:[M,K], B:[N,K] row-major)
// Output routed into up-to-3 segment pointers of width segN each.
// BM=BN=128, BK=16, 256 threads, 8x8 per thread (4+64 split).
// Single-buffered smem, 2 CTAs/SM (cross-CTA latency overlap),
// packed f32x2 accumulators (pairs along n).
// ---------------------------------------------------------------------------
#define BM 128
#define BN 128
#define BK 16

__global__ __launch_bounds__(256, 2)
void gemm_bias_nt(const float* __restrict__ A, const float* __restrict__ B,
                  const float* __restrict__ bias,
                  float* __restrict__ out0, float* __restrict__ out1,
                  float* __restrict__ out2,
                  int M, int N, int K, int segN)
{
    __shared__ __align__(16) float As[BK][BM];
    __shared__ __align__(16) float Bs[BK][BN];

    const int tid = threadIdx.x;
    const int tx  = tid & 15;
    const int ty  = tid >> 4;
    const int m0  = blockIdx.y * BM;
    const int n0  = blockIdx.x * BN;

    const float* Ab = A + (size_t)m0 * K;
    const float* Bb = B + (size_t)n0 * K;

    u64 acc2[8][4];
#pragma unroll
    for (int i = 0; i < 8; i++)
#pragma unroll
        for (int j = 0; j < 4; j++) acc2[i][j] = 0ull;

    const int ntiles = K / BK;
    for (int t = 0; t < ntiles; t++) {
        const int k0 = t * BK;
#pragma unroll
        for (int i = 0; i < 2; i++) {
            int idx = tid + i * 256;
            int row = idx >> 2;
            int kg  = (idx & 3) << 2;
            float4 av = *(const float4*)(Ab + (size_t)row * K + k0 + kg);
            As[kg + 0][row] = av.x; As[kg + 1][row] = av.y;
            As[kg + 2][row] = av.z; As[kg + 3][row] = av.w;
            float4 bv = *(const float4*)(Bb + (size_t)row * K + k0 + kg);
            Bs[kg + 0][row] = bv.x; Bs[kg + 1][row] = bv.y;
            Bs[kg + 2][row] = bv.z; Bs[kg + 3][row] = bv.w;
        }
        __syncthreads();

#pragma unroll
        for (int kk = 0; kk < BK; kk++) {
            float4 a0 = *(const float4*)&As[kk][ty * 4];
            float4 a1 = *(const float4*)&As[kk][ty * 4 + 64];
            float4 b0 = *(const float4*)&Bs[kk][tx * 4];
            float4 b1 = *(const float4*)&Bs[kk][tx * 4 + 64];
            u64 bp[4];
            bp[0] = f2_pack(b0.x, b0.y); bp[1] = f2_pack(b0.z, b0.w);
            bp[2] = f2_pack(b1.x, b1.y); bp[3] = f2_pack(b1.z, b1.w);
            float av[8] = {a0.x, a0.y, a0.z, a0.w, a1.x, a1.y, a1.z, a1.w};
#pragma unroll
            for (int i = 0; i < 8; i++) {
                u64 ad = f2_dup(av[i]);
#pragma unroll
                for (int j = 0; j < 4; j++)
                    f2_fma(acc2[i][j], ad, bp[j]);
            }
        }
        __syncthreads();
    }

    // epilogue: bias + segmented store (each 128-wide block tile lies in one segment)
#pragma unroll
    for (int i = 0; i < 8; i++) {
        const int gm = m0 + ((i < 4) ? (ty * 4 + i) : (64 + ty * 4 + (i - 4)));
#pragma unroll
        for (int jh = 0; jh < 2; jh++) {
            const int gn  = n0 + tx * 4 + jh * 64;
            const int seg = gn / segN;
            float* o = (seg == 0) ? out0 : ((seg == 1) ? out1 : out2);
            float4 v;
            f2_unpack(acc2[i][jh * 2 + 0], v.x, v.y);
            f2_unpack(acc2[i][jh * 2 + 1], v.z, v.w);
            v.x += bias[gn + 0];
            v.y += bias[gn + 1];
            v.z += bias[gn + 2];
            v.w += bias[gn + 3];
            *(float4*)(o + (size_t)gm * segN + (gn - seg * segN)) = v;
        }
    }
}

// ---------------------------------------------------------------------------
// RMSNorm over contiguous 128-float vectors: out = x * rsqrt(mean(x^2)+eps) * w
// one warp per vector
// ---------------------------------------------------------------------------
__global__ __launch_bounds__(256)
void rmsnorm128(const float* __restrict__ in, float* __restrict__ out,
                const float* __restrict__ w)
{
    const int row  = blockIdx.x * 8 + (threadIdx.x >> 5);
    const int lane = threadIdx.x & 31;
    const size_t base = (size_t)row * DHEAD + lane * 4;
    float4 xv = *(const float4*)(in + base);
    float ss = xv.x * xv.x + xv.y * xv.y + xv.z * xv.z + xv.w * xv.w;
#pragma unroll
    for (int msk = 16; msk; msk >>= 1)
        ss += __shfl_xor_sync(0xffffffffu, ss, msk);
    const float r = rsqrtf(ss * (1.0f / 128.0f) + 1e-6f);
    float4 wv = *(const float4*)(w + lane * 4);
    float4 ov;
    ov.x = xv.x * r * wv.x;
    ov.y = xv.y * r * wv.y;
    ov.z = xv.z * r * wv.z;
    ov.w = xv.w * r * wv.w;
    *(float4*)(out + base) = ov;
}

// ---------------------------------------------------------------------------
// Flash attention (non-causal, scale = 1.0), fp32 with f32x2 inner loops.
// Grid: (SEQ/BQ, NHEADS, BATCH). Block: 256 threads (16x16).
// ---------------------------------------------------------------------------
#define BQ    64
#define BKT   64
#define QPAD  132   // Qs row stride (floats)
#define KTPAD 68    // KsT row stride (floats)
#define PPAD  65    // Ps row stride (floats)

#define ATTN_SMEM_FLOATS (BQ * QPAD + DHEAD * KTPAD + BKT * DHEAD + BQ * PPAD)

__global__ __launch_bounds__(256, 1)
void attn_flash(const float* __restrict__ Q, const float* __restrict__ Kn,
                const float* __restrict__ V, float* __restrict__ Z)
{
    extern __shared__ __align__(16) float sm[];
    float* Qs  = sm;                        // [BQ][QPAD]
    float* KsT = Qs  + BQ * QPAD;           // [DHEAD][KTPAD]  (transposed K)
    float* Vs  = KsT + DHEAD * KTPAD;       // [BKT][DHEAD]
    float* Ps  = Vs  + BKT * DHEAD;         // [BQ][PPAD]

    const int tid = threadIdx.x;
    const int tx  = tid & 15;
    const int ty  = tid >> 4;
    const int qt  = blockIdx.x;
    const int h   = blockIdx.y;
    const int b   = blockIdx.z;

    const size_t rowbase = (size_t)b * SEQ;
    const int    hb      = h * DHEAD;
    const int    q0      = qt * BQ;

    // Load Q tile (reused for all K tiles)
    for (int idx = tid; idx < BQ * (DHEAD / 4); idx += 256) {
        int i  = idx >> 5;
        int d4 = (idx & 31) << 2;
        float4 v = *(const float4*)(Q + (rowbase + q0 + i) * D_MODEL + hb + d4);
        *(float4*)(Qs + i * QPAD + d4) = v;
    }

    u64 o2[4][4];   // 4 rows x 8 cols packed in pairs
    float mrow[4], lrow[4];
#pragma unroll
    for (int r = 0; r < 4; r++) {
        mrow[r] = -1e30f;
        lrow[r] = 0.f;
#pragma unroll
        for (int c = 0; c < 4; c++) o2[r][c] = 0ull;
    }

    for (int kt = 0; kt < SEQ / BKT; kt++) {
        __syncthreads();   // prior PV done reading Vs/Ps; also orders Qs on iter 0
        const int k0 = kt * BKT;
        for (int idx = tid; idx < BKT * (DHEAD / 4); idx += 256) {
            int j  = idx >> 5;
            int d4 = (idx & 31) << 2;
            float4 kv = *(const float4*)(Kn + (rowbase + k0 + j) * D_MODEL + hb + d4);
            KsT[(d4 + 0) * KTPAD + j] = kv.x;
            KsT[(d4 + 1) * KTPAD + j] = kv.y;
            KsT[(d4 + 2) * KTPAD + j] = kv.z;
            KsT[(d4 + 3) * KTPAD + j] = kv.w;
            float4 vv = *(const float4*)(V + (rowbase + k0 + j) * D_MODEL + hb + d4);
            *(float4*)(Vs + j * DHEAD + d4) = vv;
        }
        __syncthreads();

        // S = Q K^T   (4x4 per thread), d unrolled by 4, packed f32x2 over cols
        u64 s2[4][2];
#pragma unroll
        for (int r = 0; r < 4; r++) { s2[r][0] = 0ull; s2[r][1] = 0ull; }

#pragma unroll 2
        for (int d = 0; d < DHEAD; d += 4) {
            float4 qv[4], kv[4];
#pragma unroll
            for (int r = 0; r < 4; r++)
                qv[r] = *(const float4*)(Qs + (ty * 4 + r) * QPAD + d);
#pragma unroll
            for (int dd = 0; dd < 4; dd++)
                kv[dd] = *(const float4*)(KsT + (d + dd) * KTPAD + tx * 4);
#pragma unroll
            for (int dd = 0; dd < 4; dd++) {
                u64 kpA = f2_pack(kv[dd].x, kv[dd].y);
                u64 kpB = f2_pack(kv[dd].z, kv[dd].w);
#pragma unroll
                for (int r = 0; r < 4; r++) {
                    u64 qd = f2_dup(((const float*)&qv[r])[dd]);
                    f2_fma(s2[r][0], qd, kpA);
                    f2_fma(s2[r][1], qd, kpB);
                }
            }
        }

        // online softmax update (row reductions across the 16 tx lanes)
#pragma unroll
        for (int r = 0; r < 4; r++) {
            float s[4];
            f2_unpack(s2[r][0], s[0], s[1]);
            f2_unpack(s2[r][1], s[2], s[3]);
            float mx = fmaxf(fmaxf(s[0], s[1]), fmaxf(s[2], s[3]));
#pragma unroll
            for (int msk = 8; msk; msk >>= 1)
                mx = fmaxf(mx, __shfl_xor_sync(0xffffffffu, mx, msk));
            const float mnew = fmaxf(mrow[r], mx);
            const float corr = __expf(mrow[r] - mnew);
            float rs = 0.f;
#pragma unroll
            for (int c = 0; c < 4; c++) {
                float p = __expf(s[c] - mnew);
                Ps[(ty * 4 + r) * PPAD + tx * 4 + c] = p;
                rs += p;
            }
#pragma unroll
            for (int msk = 8; msk; msk >>= 1)
                rs += __shfl_xor_sync(0xffffffffu, rs, msk);
            lrow[r] = lrow[r] * corr + rs;
            mrow[r] = mnew;
            u64 cd = f2_dup(corr);
#pragma unroll
            for (int c = 0; c < 4; c++) o2[r][c] = f2_mul(o2[r][c], cd);
        }
        __syncthreads();

        // O += P V   (packed f32x2 over the 8 output cols)
#pragma unroll 4
        for (int k = 0; k < BKT; k++) {
            float4 v0 = *(const float4*)(Vs + k * DHEAD + tx * 8);
            float4 v1 = *(const float4*)(Vs + k * DHEAD + tx * 8 + 4);
            u64 vp[4];
            vp[0] = f2_pack(v0.x, v0.y); vp[1] = f2_pack(v0.z, v0.w);
            vp[2] = f2_pack(v1.x, v1.y); vp[3] = f2_pack(v1.z, v1.w);
#pragma unroll
            for (int r = 0; r < 4; r++) {
                u64 pd = f2_dup(Ps[(ty * 4 + r) * PPAD + k]);
                f2_fma(o2[r][0], pd, vp[0]);
                f2_fma(o2[r][1], pd, vp[1]);
                f2_fma(o2[r][2], pd, vp[2]);
                f2_fma(o2[r][3], pd, vp[3]);
            }
        }
    }

    // normalize and write Z in [b, s, h*dh] layout
#pragma unroll
    for (int r = 0; r < 4; r++) {
        const float inv = 1.f / lrow[r];
        float4 w0, w1;
        f2_unpack(o2[r][0], w0.x, w0.y);
        f2_unpack(o2[r][1], w0.z, w0.w);
        f2_unpack(o2[r][2], w1.x, w1.y);
        f2_unpack(o2[r][3], w1.z, w1.w);
        w0.x *= inv; w0.y *= inv; w0.z *= inv; w0.w *= inv;
        w1.x *= inv; w1.y *= inv; w1.z *= inv; w1.w *= inv;
        const size_t base = (rowbase + q0 + ty * 4 + r) * D_MODEL + hb + tx * 8;
        *(float4*)(Z + base)     = w0;
        *(float4*)(Z + base + 4) = w1;
    }
}

// ---------------------------------------------------------------------------
// Launch
// Inputs (metadata order): x, W_qkv, b_qkv, W_o, b_o, wq, wk   (all fp32)
// Output: [out | k_new | v_new], each MTOT*D_MODEL floats.
// ---------------------------------------------------------------------------
extern "C" void kernel_launch(void* const* d_in, const int* in_sizes, int n_in,
                              void* d_out, int out_size)
{
    const float* x    = (const float*)d_in[0];
    const float* Wqkv = (const float*)d_in[1];
    const float* bqkv = (const float*)d_in[2];
    const float* Wo   = (const float*)d_in[3];
    const float* bo   = (const float*)d_in[4];
    const float* wq   = (const float*)d_in[5];
    const float* wk   = (const float*)d_in[6];

    float* out  = (float*)d_out;
    float* kout = out + (size_t)OUTSZ;       // k_new (pre-norm)
    float* vout = out + (size_t)2 * OUTSZ;   // v_new

    float *qbuf = nullptr, *knbuf = nullptr, *zbuf = nullptr;
    cudaGetSymbolAddress((void**)&qbuf,  g_q);
    cudaGetSymbolAddress((void**)&knbuf, g_kn);
    cudaGetSymbolAddress((void**)&zbuf,  g_z);

    // 1) QKV projection: q -> scratch, k/v -> their output regions directly
    gemm_bias_nt<<<dim3(3 * D_MODEL / BN, MTOT / BM), 256>>>(
        x, Wqkv, bqkv, qbuf, kout, vout,
        MTOT, 3 * D_MODEL, D_MODEL, D_MODEL);

    // 2) per-head RMSNorm on q (in place) and k (into scratch)
    rmsnorm128<<<(MTOT * NHEADS) / 8, 256>>>(qbuf, qbuf, wq);
    rmsnorm128<<<(MTOT * NHEADS) / 8, 256>>>(kout, knbuf, wk);

    // 3) flash attention -> z scratch
    const int attn_smem = ATTN_SMEM_FLOATS * (int)sizeof(float);
    cudaFuncSetAttribute(attn_flash,
                         cudaFuncAttributeMaxDynamicSharedMemorySize, attn_smem);
    attn_flash<<<dim3(SEQ / BQ, NHEADS, BATCH), 256, attn_smem>>>(
        qbuf, knbuf, vout, zbuf);

    // 4) output projection
    gemm_bias_nt<<<dim3(D_MODEL / BN, MTOT / BM), 256>>>(
        zbuf, Wo, bo, out, out, out,
        MTOT, D_MODEL, D_MODEL, D_MODEL);
}